// round 15
// baseline (speedup 1.0000x reference)
#include <cuda_runtime.h>
#include <math.h>

#define NB    4
#define NIM   5
#define NTRI  12288
#define PTOK  256
#define IMGC  1280
#define EMB   128
#define NROWS (NB * NTRI)

// ------------------- scratch (device globals, no allocs) -------------------
__device__ float g_pe_imgK[256 * 128];             // pe_img + k_b
__device__ float g_pe_imgV[256 * 128];             // pe_img + v_b
__device__ float g_pe_triT[128 * NTRI];            // (pe_tri + q_b)^T  [c][n]
__device__ float g_WkT[128 * 128];                 // Wk^T
__device__ float g_WvT[128 * 128];                 // Wv^T
__device__ float g_WcT[IMGC * 256];                // [e][0:128]=Wk@k_w, [128:256]=Wv@v_w (K-major)
__device__ float g_WcatT[192 * 128];               // [k][i]: k<64 -> Wqc^T, else Wq^T
__device__ float g_WocT[128 * 64];                 // (conv_w@out_w)^T
__device__ float g_bKV[256 * 256];                 // [p][c] combined bias+pe for kv'
__device__ float g_boc[64];
__device__ float g_imgT[20LL * IMGC * 256];        // img tokens transposed  [g][k][p]  26MB
__device__ float g_vol[(size_t)NB * NIM * PTOK * 256];   // volKV' 5.2MB
__device__ float g_qp [(size_t)NROWS * EMB];       // 25MB
__device__ float g_oT [(size_t)EMB * NROWS];       // attention out, K-major  25MB

// ------------------- f32x2 helpers ------------------------------------------
__device__ __forceinline__ unsigned long long fma2(unsigned long long a,
                                                   unsigned long long b,
                                                   unsigned long long c) {
    unsigned long long d;
    asm("fma.rn.f32x2 %0, %1, %2, %3;" : "=l"(d) : "l"(a), "l"(b), "l"(c));
    return d;
}
__device__ __forceinline__ unsigned long long packdup(float x) {
    unsigned long long d;
    unsigned int u = __float_as_uint(x);
    asm("mov.b64 %0, {%1, %2};" : "=l"(d) : "r"(u), "r"(u));
    return d;
}
__device__ __forceinline__ void unpack2(unsigned long long v, float& lo, float& hi) {
    unsigned int a, b;
    asm("mov.b64 {%0, %1}, %2;" : "=r"(a), "=r"(b) : "l"(v));
    lo = __uint_as_float(a); hi = __uint_as_float(b);
}

// ------------------- fast fp32 positional encoding --------------------------
__device__ __forceinline__ float pe_val(int pos, int c) {
    int i = c >> 1;
    float divf = expf((float)(2 * i) * (-0.07195578415606394f));
    float a = (float)pos * divf;
    float kf = rintf(a * 0.6366197723675814f);
    float r = fmaf(-kf, 1.57079637050628662109375f, a);
    r = fmaf(-kf, -4.37113900018624283e-8f, r);
    float z = r * r;
    float p = fmaf(-1.9515295891e-4f, z, 8.3321608736e-3f);
    p = fmaf(p, z, -1.6666654611e-1f);
    float ps = fmaf(p * z, r, r);
    float q2 = fmaf(2.443315711809948e-5f, z, -1.388731625493765e-3f);
    q2 = fmaf(q2, z, 4.166664568298827e-2f);
    float pc = fmaf(q2, z * z, fmaf(-0.5f, z, 1.f));
    int qi = ((int)kf + (c & 1)) & 3;
    float res = (qi & 1) ? pc : ps;
    return (qi & 2) ? -res : res;
}

__global__ __launch_bounds__(256) void pe_fill_kernel(
    const float* __restrict__ q_b, const float* __restrict__ k_b,
    const float* __restrict__ v_b)
{
    int idx = blockIdx.x * 256 + threadIdx.x;
    if (idx < 256 * 128) {
        int r = idx >> 7, c = idx & 127;
        float v = pe_val(r, c);
        g_pe_imgK[idx] = v + k_b[c];
        g_pe_imgV[idx] = v + v_b[c];
    } else {
        int local = idx - 256 * 128;           // c * NTRI + n
        int c = local / NTRI, n = local - c * NTRI;
        g_pe_triT[local] = pe_val(n, c) + q_b[c];
    }
}

// ------------------- transposes: in_wT (Wk,Wv) + imgT ------------------------
__global__ __launch_bounds__(256) void transpose_all_kernel(
    const float* __restrict__ in_w, const float* __restrict__ img)
{
    __shared__ float s[32][33];
    int bid = blockIdx.x;
    int tid = threadIdx.x;
    int tx = tid & 31, ty = tid >> 5;
    if (bid < 32) {                      // Wk / Wv 128x128 transposes
        const float* src = in_w + (bid < 16 ? 128 * 128 : 256 * 128);
        float* dst = (bid < 16) ? g_WkT : g_WvT;
        int t = bid & 15;
        int r0 = (t >> 2) * 32, c0 = (t & 3) * 32;
#pragma unroll
        for (int i = 0; i < 4; i++)
            s[ty + i * 8][tx] = src[(r0 + ty + i * 8) * 128 + c0 + tx];
        __syncthreads();
#pragma unroll
        for (int i = 0; i < 4; i++)
            dst[(c0 + ty + i * 8) * 128 + r0 + tx] = s[tx][ty + i * 8];
    } else {                             // imgT: per (b,j) transpose 256x1280 -> 1280x256
        int t = bid - 32;                // 20 groups x 320 tiles
        int g = t / 320; t -= g * 320;
        int k0 = (t >> 3) * 32;          // 40 k-tiles
        int p0 = (t & 7) * 32;           // 8 p-tiles
        const float* src = img + (size_t)g * 257 * IMGC + IMGC;   // skip CLS
#pragma unroll
        for (int i = 0; i < 4; i++)
            s[ty + i * 8][tx] = src[(size_t)(p0 + ty + i * 8) * IMGC + k0 + tx];
        __syncthreads();
        float* dst = g_imgT + (size_t)g * IMGC * 256;
#pragma unroll
        for (int i = 0; i < 4; i++)
            dst[(size_t)(k0 + ty + i * 8) * 256 + p0 + tx] = s[tx][ty + i * 8];
    }
}

// ------------------- merged small precompute --------------------------------
// blocks [0,256): bKV row p ; [256,352): WcatT ; [352,384): WocT ; 384: boc
__global__ __launch_bounds__(256) void small_all_kernel(
    const float* __restrict__ in_w, const float* __restrict__ in_b,
    const float* __restrict__ q_w,
    const float* __restrict__ out_w, const float* __restrict__ out_b,
    const float* __restrict__ conv_w, const float* __restrict__ conv_b)
{
    const float* Wq = in_w;
    const float* Wk = in_w + 128 * 128;
    const float* Wv = in_w + 256 * 128;
    int bid = blockIdx.x, tid = threadIdx.x;
    if (bid < 256) {
        __shared__ float peK[128], peV[128];
        if (tid < 128) peK[tid] = g_pe_imgK[bid * 128 + tid];
        else           peV[tid - 128] = g_pe_imgV[bid * 128 + tid - 128];
        __syncthreads();
        float s;
        if (tid < 128) {
            s = in_b[128 + tid];
            const float* wr = Wk + tid * 128;
            for (int e = 0; e < 128; e++) s = fmaf(wr[e], peK[e], s);
        } else {
            int c = tid - 128;
            s = in_b[256 + c];
            const float* wr = Wv + c * 128;
            for (int e = 0; e < 128; e++) s = fmaf(wr[e], peV[e], s);
        }
        g_bKV[bid * 256 + tid] = s;
    } else if (bid < 352) {
        int idx = (bid - 256) * 256 + tid;   // 192*128, k*128+i
        int k = idx >> 7, i = idx & 127;
        float s;
        if (k < 64) {
            s = 0.f;
            for (int e = 0; e < 128; e++)
                s = fmaf(Wq[i * 128 + e], q_w[e * 64 + k], s);
        } else {
            s = Wq[i * 128 + (k - 64)];
        }
        g_WcatT[idx] = s;
    } else if (bid < 384) {
        int idx = (bid - 352) * 256 + tid;   // 128*64, c*64+oc
        int c = idx >> 6, oc = idx & 63;
        float s = 0.f;
        for (int d = 0; d < 128; d++)
            s = fmaf(conv_w[oc * 128 + d], out_w[d * 128 + c], s);
        g_WocT[idx] = s;
    } else if (tid < 64) {
        float s = conv_b[tid];
        for (int d = 0; d < 128; d++)
            s = fmaf(conv_w[tid * 128 + d], out_b[d], s);
        g_boc[tid] = s;
    }
}

// ------------------- FFMA2 SGEMM: K-major operands ---------------------------
struct GCfg {
    const float* A1; long long gdiv; long long gstride; int lda1;
    const float* A2; int lda2; long long mod2; int kSplit;
    const float* W; int ldw;
    const float* bias; const float* T; int t_mod; int ldt;
    float* C; int ldc; int K; int ny; int trans_rows;
};

__global__ __launch_bounds__(128, 4) void gemm_f2_kernel(GCfg c0, GCfg c1, int count0)
{
    const bool first = (blockIdx.x < (unsigned)count0);
    GCfg cfg = first ? c0 : c1;
    const int local = first ? blockIdx.x : blockIdx.x - count0;

    __shared__ __align__(16) float As[2][16][68];
    __shared__ __align__(16) float Ws[2][16][68];

    const int tid = threadIdx.x;
    const int tx = tid & 15, ty = tid >> 4;
    const int m0 = (local / cfg.ny) * 64;
    const int n0 = (local % cfg.ny) * 64;

    const int kr = tid >> 3;
    const int cq = (tid & 7) * 8;
    const long long cm = m0 + cq;
    const float* base1 = cfg.A1 + (cm / cfg.gdiv) * cfg.gstride + (cm % cfg.gdiv);
    const float* base2 = cfg.A2 ? (cfg.A2 + (cm % cfg.mod2)) : nullptr;
    const float* wbase = cfg.W + n0 + cq;
    const bool concat = (cfg.A2 != nullptr);

    unsigned long long acc[4][4];
#pragma unroll
    for (int i = 0; i < 4; i++)
#pragma unroll
        for (int j = 0; j < 4; j++) acc[i][j] = 0ULL;

    const int nk = cfg.K / 16;

    float4 a0, a1, w0, w1;
    {
        int kk = kr;
        const float* p = (concat && kk >= cfg.kSplit)
            ? base2 + (size_t)(kk - cfg.kSplit) * cfg.lda2
            : base1 + (size_t)kk * cfg.lda1;
        a0 = *(const float4*)p; a1 = *(const float4*)(p + 4);
        const float* q = wbase + (size_t)kk * cfg.ldw;
        w0 = *(const float4*)q; w1 = *(const float4*)(q + 4);
    }
    *(float4*)&As[0][kr][cq]     = a0;
    *(float4*)&As[0][kr][cq + 4] = a1;
    *(float4*)&Ws[0][kr][cq]     = w0;
    *(float4*)&Ws[0][kr][cq + 4] = w1;
    __syncthreads();

    for (int it = 0; it < nk; ++it) {
        const int cur = it & 1;
        const bool more = (it + 1 < nk);
        if (more) {
            int kk = (it + 1) * 16 + kr;
            const float* p = (concat && kk >= cfg.kSplit)
                ? base2 + (size_t)(kk - cfg.kSplit) * cfg.lda2
                : base1 + (size_t)kk * cfg.lda1;
            a0 = *(const float4*)p; a1 = *(const float4*)(p + 4);
            const float* q = wbase + (size_t)kk * cfg.ldw;
            w0 = *(const float4*)q; w1 = *(const float4*)(q + 4);
        }
#pragma unroll
        for (int k = 0; k < 16; ++k) {
            const float* arow = &As[cur][k][ty * 8];
            ulonglong2 p0 = *(const ulonglong2*)arow;
            ulonglong2 p1 = *(const ulonglong2*)(arow + 4);
            unsigned long long a2[4] = {p0.x, p0.y, p1.x, p1.y};
            float4 u = *(const float4*)&Ws[cur][k][tx * 4];
            unsigned long long w2[4] = {packdup(u.x), packdup(u.y),
                                        packdup(u.z), packdup(u.w)};
#pragma unroll
            for (int i = 0; i < 4; i++)
#pragma unroll
                for (int j = 0; j < 4; j++)
                    acc[i][j] = fma2(a2[i], w2[j], acc[i][j]);
        }
        if (more) {
            const int nxt = (it + 1) & 1;
            *(float4*)&As[nxt][kr][cq]     = a0;
            *(float4*)&As[nxt][kr][cq + 4] = a1;
            *(float4*)&Ws[nxt][kr][cq]     = w0;
            *(float4*)&Ws[nxt][kr][cq + 4] = w1;
        }
        __syncthreads();
    }

#pragma unroll
    for (int i = 0; i < 4; i++) {
        float clo[4], chi[4];
#pragma unroll
        for (int j = 0; j < 4; j++) unpack2(acc[i][j], clo[j], chi[j]);
#pragma unroll
        for (int h = 0; h < 2; h++) {
            const int m = m0 + ty * 8 + i * 2 + h;
            const int mt = cfg.T ? (m % cfg.t_mod) : 0;
            float4 v;
            float* vp = (float*)&v;
#pragma unroll
            for (int j = 0; j < 4; j++) {
                const int gn = n0 + tx * 4 + j;
                float x = h ? chi[j] : clo[j];
                if (cfg.bias) x += cfg.bias[gn];
                if (cfg.T)    x += cfg.T[(size_t)mt * cfg.ldt + gn];
                vp[j] = x;
            }
            *(float4*)(cfg.C + (size_t)m * cfg.ldc + n0 + tx * 4) = v;
        }
    }
}

// ------------------- dedicated final GEMM (K=128, N=64, transposed store) ----
__global__ __launch_bounds__(128, 5) void final_kernel(
    const float* __restrict__ oT, const float* __restrict__ WocT,
    const float* __restrict__ boc, float* __restrict__ out)
{
    __shared__ __align__(16) float SM[4 * 16 * 68];   // 17408B; Cs overlays
    float (*As)[16][68] = reinterpret_cast<float(*)[16][68]>(SM);
    float (*Ws)[16][68] = reinterpret_cast<float(*)[16][68]>(SM + 2 * 16 * 68);

    const int tid = threadIdx.x;
    const int tx = tid & 15, ty = tid >> 4;
    const int m0 = blockIdx.x * 64;

    const int kr = tid >> 3;
    const int cq = (tid & 7) * 8;
    const float* abase = oT + m0 + cq;          // + kk*NROWS
    const float* wbase = WocT + cq;             // + kk*64

    unsigned long long acc[4][4];
#pragma unroll
    for (int i = 0; i < 4; i++)
#pragma unroll
        for (int j = 0; j < 4; j++) acc[i][j] = 0ULL;

    float4 a0, a1, w0, w1;
    a0 = *(const float4*)(abase + (size_t)kr * NROWS);
    a1 = *(const float4*)(abase + (size_t)kr * NROWS + 4);
    w0 = *(const float4*)(wbase + (size_t)kr * 64);
    w1 = *(const float4*)(wbase + (size_t)kr * 64 + 4);
    *(float4*)&As[0][kr][cq]     = a0;
    *(float4*)&As[0][kr][cq + 4] = a1;
    *(float4*)&Ws[0][kr][cq]     = w0;
    *(float4*)&Ws[0][kr][cq + 4] = w1;
    __syncthreads();

    for (int it = 0; it < 8; ++it) {            // NOT unrolled: small I$ body
        const int cur = it & 1;
        if (it + 1 < 8) {
            int kk = (it + 1) * 16 + kr;
            a0 = *(const float4*)(abase + (size_t)kk * NROWS);
            a1 = *(const float4*)(abase + (size_t)kk * NROWS + 4);
            w0 = *(const float4*)(wbase + (size_t)kk * 64);
            w1 = *(const float4*)(wbase + (size_t)kk * 64 + 4);
        }
#pragma unroll
        for (int k = 0; k < 16; ++k) {
            const float* arow = &As[cur][k][ty * 8];
            ulonglong2 p0 = *(const ulonglong2*)arow;
            ulonglong2 p1 = *(const ulonglong2*)(arow + 4);
            unsigned long long a2[4] = {p0.x, p0.y, p1.x, p1.y};
            float4 u = *(const float4*)&Ws[cur][k][tx * 4];
            unsigned long long w2[4] = {packdup(u.x), packdup(u.y),
                                        packdup(u.z), packdup(u.w)};
#pragma unroll
            for (int i = 0; i < 4; i++)
#pragma unroll
                for (int j = 0; j < 4; j++)
                    acc[i][j] = fma2(a2[i], w2[j], acc[i][j]);
        }
        if (it + 1 < 8) {
            const int nxt = (it + 1) & 1;
            *(float4*)&As[nxt][kr][cq]     = a0;
            *(float4*)&As[nxt][kr][cq + 4] = a1;
            *(float4*)&Ws[nxt][kr][cq]     = w0;
            *(float4*)&Ws[nxt][kr][cq + 4] = w1;
        }
        __syncthreads();
    }

    // stage 64x64 tile in smem (overlaid), then coalesced transposed store
    float (*Cs)[65] = reinterpret_cast<float(*)[65]>(SM);
#pragma unroll
    for (int i = 0; i < 4; i++) {
        float clo[4], chi[4];
#pragma unroll
        for (int j = 0; j < 4; j++) unpack2(acc[i][j], clo[j], chi[j]);
#pragma unroll
        for (int j = 0; j < 4; j++) {
            const float bb = boc[tx * 4 + j];
            Cs[ty * 8 + i * 2 + 0][tx * 4 + j] = clo[j] + bb;
            Cs[ty * 8 + i * 2 + 1][tx * 4 + j] = chi[j] + bb;
        }
    }
    __syncthreads();
    const int oc = tid >> 1, half = tid & 1;
    const int bb = m0 / NTRI;
    const int nn0 = m0 - bb * NTRI;
    float* base = out + (size_t)(bb * 64 + oc) * NTRI + nn0 + half * 32;
#pragma unroll
    for (int s = 0; s < 8; s++) {
        float4 v;
        v.x = Cs[half * 32 + s * 4 + 0][oc];
        v.y = Cs[half * 32 + s * 4 + 1][oc];
        v.z = Cs[half * 32 + s * 4 + 2][oc];
        v.w = Cs[half * 32 + s * 4 + 3][oc];
        *(float4*)(base + s * 4) = v;
    }
}

// ------------------- fused sample + attention (writes oT) --------------------
__global__ __launch_bounds__(256) void fused_attn_kernel(const float* __restrict__ proj)
{
    __shared__ float Ps[NIM][12];
    __shared__ float o_s[8][132];
    const int b = blockIdx.y;
    if (threadIdx.x < NIM * 12) {
        int j = threadIdx.x / 12, e = threadIdx.x - j * 12;
        Ps[j][e] = proj[((size_t)(b * NIM + j) * 4 + (e >> 2)) * 4 + (e & 3)];
    }
    __syncthreads();

    const int lane = threadIdx.x & 31;
    const int wp = threadIdx.x >> 5;
    const int n = blockIdx.x * 8 + wp;

    const int plane = n >> 12;
    const int loc = n & 4095;
    const float colf = (float)(loc & 63);
    const float rowf = (float)(loc >> 6);
    float vx, vy, vz;
    if (plane == 0)      { vx = colf;  vy = 31.5f; vz = rowf; }
    else if (plane == 1) { vx = colf;  vy = rowf;  vz = 31.5f; }
    else                 { vx = 31.5f; vy = colf;  vz = rowf; }
    const float SC = (float)(2.0 * (1.0 + 0.1 + 1e-05));
    const float cx = (vx / 63.0f - 0.5f) * SC;
    const float cy = (vy / 63.0f - 0.5f) * SC;
    const float cz = (vz / 63.0f - 0.5f) * SC;

    const float4 q4 = *(const float4*)(g_qp + ((size_t)(b * NTRI + n)) * 128 + lane * 4);

    float4 vkeep[NIM];
    float score[NIM];

#pragma unroll
    for (int j = 0; j < NIM; ++j) {
        const float* P = Ps[j];
        float ci0 = cx * P[0] + cy * P[1] + cz * P[2]  + P[3];
        float ci1 = cx * P[4] + cy * P[5] + cz * P[6]  + P[7];
        float ci2 = cx * P[8] + cy * P[9] + cz * P[10] + P[11];
        float x = ci0 / ci2 / 223.0f;
        float y = ci1 / ci2 / 223.0f;
        float gx = fminf(fmaxf((x - 0.5f) * 2.0f, -1.0f), 1.0f);
        float gy = fminf(fmaxf((y - 0.5f) * 2.0f, -1.0f), 1.0f);
        float ix = (gx + 1.0f) * 7.5f;
        float iy = (gy + 1.0f) * 7.5f;
        float x0f = floorf(ix), y0f = floorf(iy);
        float wx = ix - x0f, wy = iy - y0f;
        int x0 = min(max((int)x0f, 0), 15);
        int x1 = min(x0 + 1, 15);
        int y0 = min(max((int)y0f, 0), 15);
        int y1 = min(y0 + 1, 15);
        float w00 = (1.f - wy) * (1.f - wx);
        float w01 = (1.f - wy) * wx;
        float w10 = wy * (1.f - wx);
        float w11 = wy * wx;

        const float* base = g_vol + (size_t)(b * NIM + j) * PTOK * 256;
        const int t00 = (y0 * 16 + x0) * 256, t01 = (y0 * 16 + x1) * 256;
        const int t10 = (y1 * 16 + x0) * 256, t11 = (y1 * 16 + x1) * 256;
        const int ck = lane * 4;

        float4 k00 = *(const float4*)(base + t00 + ck);
        float4 k01 = *(const float4*)(base + t01 + ck);
        float4 k10 = *(const float4*)(base + t10 + ck);
        float4 k11 = *(const float4*)(base + t11 + ck);

        float d00 = q4.x*k00.x; d00 = fmaf(q4.y,k00.y,d00); d00 = fmaf(q4.z,k00.z,d00); d00 = fmaf(q4.w,k00.w,d00);
        float d01 = q4.x*k01.x; d01 = fmaf(q4.y,k01.y,d01); d01 = fmaf(q4.z,k01.z,d01); d01 = fmaf(q4.w,k01.w,d01);
        float d10 = q4.x*k10.x; d10 = fmaf(q4.y,k10.y,d10); d10 = fmaf(q4.z,k10.z,d10); d10 = fmaf(q4.w,k10.w,d10);
        float d11 = q4.x*k11.x; d11 = fmaf(q4.y,k11.y,d11); d11 = fmaf(q4.z,k11.z,d11); d11 = fmaf(q4.w,k11.w,d11);
        float d = w00*d00; d = fmaf(w01,d01,d); d = fmaf(w10,d10,d); d = fmaf(w11,d11,d);
        d += __shfl_xor_sync(0xffffffffu, d, 1);
        d += __shfl_xor_sync(0xffffffffu, d, 2);
        score[j] = d * 0.25f;

        float4 v00 = *(const float4*)(base + t00 + 128 + ck);
        float4 v01 = *(const float4*)(base + t01 + 128 + ck);
        float4 v10 = *(const float4*)(base + t10 + 128 + ck);
        float4 v11 = *(const float4*)(base + t11 + 128 + ck);
        float4 vv;
        vv.x = w00*v00.x; vv.x = fmaf(w01,v01.x,vv.x); vv.x = fmaf(w10,v10.x,vv.x); vv.x = fmaf(w11,v11.x,vv.x);
        vv.y = w00*v00.y; vv.y = fmaf(w01,v01.y,vv.y); vv.y = fmaf(w10,v10.y,vv.y); vv.y = fmaf(w11,v11.y,vv.y);
        vv.z = w00*v00.z; vv.z = fmaf(w01,v01.z,vv.z); vv.z = fmaf(w10,v10.z,vv.z); vv.z = fmaf(w11,v11.z,vv.z);
        vv.w = w00*v00.w; vv.w = fmaf(w01,v01.w,vv.w); vv.w = fmaf(w10,v10.w,vv.w); vv.w = fmaf(w11,v11.w,vv.w);
        vkeep[j] = vv;
    }

    float mx = score[0];
#pragma unroll
    for (int j = 1; j < NIM; j++) mx = fmaxf(mx, score[j]);
    float sum = 0.f;
#pragma unroll
    for (int j = 0; j < NIM; j++) { score[j] = __expf(score[j] - mx); sum += score[j]; }
    const float inv = 1.f / sum;

    float4 o = make_float4(0.f, 0.f, 0.f, 0.f);
#pragma unroll
    for (int j = 0; j < NIM; j++) {
        float w = score[j] * inv;
        o.x = fmaf(w, vkeep[j].x, o.x);
        o.y = fmaf(w, vkeep[j].y, o.y);
        o.z = fmaf(w, vkeep[j].z, o.z);
        o.w = fmaf(w, vkeep[j].w, o.w);
    }
    o_s[wp][lane * 4 + 0] = o.x;
    o_s[wp][lane * 4 + 1] = o.y;
    o_s[wp][lane * 4 + 2] = o.z;
    o_s[wp][lane * 4 + 3] = o.w;
    __syncthreads();

    const int c = threadIdx.x >> 1, h = threadIdx.x & 1;
    float4 v;
    v.x = o_s[h * 4 + 0][c];
    v.y = o_s[h * 4 + 1][c];
    v.z = o_s[h * 4 + 2][c];
    v.w = o_s[h * 4 + 3][c];
    *(float4*)(g_oT + (size_t)c * NROWS + (size_t)b * NTRI + blockIdx.x * 8 + h * 4) = v;
}

// ------------------- launch -------------------------------------------------
extern "C" void kernel_launch(void* const* d_in, const int* in_sizes, int n_in,
                              void* d_out, int out_size)
{
    const float* tf     = (const float*)d_in[0];
    const float* img    = (const float*)d_in[1];
    const float* proj   = (const float*)d_in[2];
    const float* k_w    = (const float*)d_in[4];
    const float* k_b    = (const float*)d_in[5];
    const float* q_w    = (const float*)d_in[6];
    const float* q_b    = (const float*)d_in[7];
    const float* v_w    = (const float*)d_in[8];
    const float* v_b    = (const float*)d_in[9];
    const float* in_w   = (const float*)d_in[10];
    const float* in_b   = (const float*)d_in[11];
    const float* out_w  = (const float*)d_in[12];
    const float* out_b  = (const float*)d_in[13];
    const float* conv_w = (const float*)d_in[14];
    const float* conv_b = (const float*)d_in[15];
    float* out = (float*)d_out;

    float *p_WkT, *p_WvT, *p_WcT, *p_WcatT, *p_WocT, *p_bKV, *p_boc;
    float *p_pe_triT, *p_imgT, *p_vol, *p_qp, *p_oT;
    cudaGetSymbolAddress((void**)&p_WkT, g_WkT);
    cudaGetSymbolAddress((void**)&p_WvT, g_WvT);
    cudaGetSymbolAddress((void**)&p_WcT, g_WcT);
    cudaGetSymbolAddress((void**)&p_WcatT, g_WcatT);
    cudaGetSymbolAddress((void**)&p_WocT, g_WocT);
    cudaGetSymbolAddress((void**)&p_bKV, g_bKV);
    cudaGetSymbolAddress((void**)&p_boc, g_boc);
    cudaGetSymbolAddress((void**)&p_pe_triT, g_pe_triT);
    cudaGetSymbolAddress((void**)&p_imgT, g_imgT);
    cudaGetSymbolAddress((void**)&p_vol, g_vol);
    cudaGetSymbolAddress((void**)&p_qp,  g_qp);
    cudaGetSymbolAddress((void**)&p_oT,  g_oT);

    const long long BIG = 1LL << 60;

    // fork/join resources (host objects only; created per call, intentionally
    // not destroyed mid-capture — no device memory is involved)
    cudaStream_t s1;
    cudaStreamCreateWithFlags(&s1, cudaStreamNonBlocking);
    cudaEvent_t evFork, evJoin;
    cudaEventCreateWithFlags(&evFork, cudaEventDisableTiming);
    cudaEventCreateWithFlags(&evJoin, cudaEventDisableTiming);

    // fork side stream off the (captured) legacy stream
    cudaEventRecord(evFork, 0);
    cudaStreamWaitEvent(s1, evFork, 0);

    // SIDE spine: L1 pe tables -> L3 small precomputes
    pe_fill_kernel<<<(256 * 128 + 128 * NTRI) / 256, 256, 0, s1>>>(q_b, k_b, v_b);
    small_all_kernel<<<385, 256, 0, s1>>>(in_w, in_b, q_w, out_w, out_b,
                                          conv_w, conv_b);
    cudaEventRecord(evJoin, s1);

    // MAIN spine: L2 transposes -> L4 WcT GEMM (runs concurrently with side)
    transpose_all_kernel<<<32 + 20 * 320, 256>>>(in_w, img);
    {
        GCfg ck = { k_w, BIG, 0, IMGC,  nullptr, 0, 1, 1 << 30,
                    p_WkT, 128, nullptr, nullptr, 1, 1,
                    p_WcT, 256, 128, 2, 0 };
        GCfg cv = { v_w, BIG, 0, IMGC,  nullptr, 0, 1, 1 << 30,
                    p_WvT, 128, nullptr, nullptr, 1, 1,
                    p_WcT + 128, 256, 128, 2, 0 };
        gemm_f2_kernel<<<80, 128>>>(ck, cv, 40);
    }

    // join: main stream waits for side spine before the mega GEMM
    cudaStreamWaitEvent(0, evJoin, 0);

    // L5: mega GEMM: volKV (320 CTAs) + qp (1536 CTAs)
    {
        GCfg cvol = { p_imgT, 256, 1280LL * 256, 256,  nullptr, 0, 1, 1 << 30,
                      p_WcT, 256, nullptr, p_bKV, 256, 256,
                      p_vol, 256, IMGC, 4, 0 };
        GCfg cqp  = { tf, NTRI, 64LL * NTRI, NTRI,  p_pe_triT, NTRI, NTRI, 64,
                      p_WcatT, 128, in_b, nullptr, 1, 1,
                      p_qp, 128, 192, 2, 0 };
        gemm_f2_kernel<<<320 + 1536, 128>>>(cvol, cqp, 320);
    }

    // L6: fused sample + attention -> oT
    fused_attn_kernel<<<dim3(NTRI / 8, NB), 256>>>(proj);

    // L7: dedicated final GEMM (low-reg, overlaid smem, bounded I$ body)
    final_kernel<<<768, 128>>>(p_oT, p_WocT, p_boc, out);
}

// round 16
// speedup vs baseline: 1.1373x; 1.1373x over previous
#include <cuda_runtime.h>
#include <math.h>

#define NB    4
#define NIM   5
#define NTRI  12288
#define PTOK  256
#define IMGC  1280
#define EMB   128
#define NROWS (NB * NTRI)

// ------------------- scratch (device globals, no allocs) -------------------
__device__ float g_pe_imgK[256 * 128];             // pe_img + k_b
__device__ float g_pe_imgV[256 * 128];             // pe_img + v_b
__device__ float g_pe_triT[128 * NTRI];            // (pe_tri + q_b)^T  [c][n]
__device__ float g_WkT[128 * 128];                 // Wk^T
__device__ float g_WvT[128 * 128];                 // Wv^T
__device__ float g_WcT[IMGC * 256];                // [e][0:128]=Wk@k_w, [128:256]=Wv@v_w (K-major)
__device__ float g_WcatT[192 * 128];               // [k][i]: k<64 -> Wqc^T, else Wq^T
__device__ float g_WocT[128 * 64];                 // (conv_w@out_w)^T
__device__ float g_bKV[256 * 256];                 // [p][c] combined bias+pe for kv'
__device__ float g_boc[64];
__device__ float g_imgT[20LL * IMGC * 256];        // img tokens transposed  [g][k][p]  26MB
__device__ float g_vol[(size_t)NB * NIM * PTOK * 256];   // volKV' 5.2MB
__device__ float g_qp [(size_t)NROWS * EMB];       // 25MB
__device__ float g_oT [(size_t)EMB * NROWS];       // attention out, K-major  25MB

// ------------------- f32x2 helpers ------------------------------------------
__device__ __forceinline__ unsigned long long fma2(unsigned long long a,
                                                   unsigned long long b,
                                                   unsigned long long c) {
    unsigned long long d;
    asm("fma.rn.f32x2 %0, %1, %2, %3;" : "=l"(d) : "l"(a), "l"(b), "l"(c));
    return d;
}
__device__ __forceinline__ unsigned long long packdup(float x) {
    unsigned long long d;
    unsigned int u = __float_as_uint(x);
    asm("mov.b64 %0, {%1, %2};" : "=l"(d) : "r"(u), "r"(u));
    return d;
}
__device__ __forceinline__ void unpack2(unsigned long long v, float& lo, float& hi) {
    unsigned int a, b;
    asm("mov.b64 {%0, %1}, %2;" : "=r"(a), "=r"(b) : "l"(v));
    lo = __uint_as_float(a); hi = __uint_as_float(b);
}

// ------------------- fast fp32 positional encoding --------------------------
__device__ __forceinline__ float pe_val(int pos, int c) {
    int i = c >> 1;
    float divf = expf((float)(2 * i) * (-0.07195578415606394f));
    float a = (float)pos * divf;
    float kf = rintf(a * 0.6366197723675814f);
    float r = fmaf(-kf, 1.57079637050628662109375f, a);
    r = fmaf(-kf, -4.37113900018624283e-8f, r);
    float z = r * r;
    float p = fmaf(-1.9515295891e-4f, z, 8.3321608736e-3f);
    p = fmaf(p, z, -1.6666654611e-1f);
    float ps = fmaf(p * z, r, r);
    float q2 = fmaf(2.443315711809948e-5f, z, -1.388731625493765e-3f);
    q2 = fmaf(q2, z, 4.166664568298827e-2f);
    float pc = fmaf(q2, z * z, fmaf(-0.5f, z, 1.f));
    int qi = ((int)kf + (c & 1)) & 3;
    float res = (qi & 1) ? pc : ps;
    return (qi & 2) ? -res : res;
}

__global__ __launch_bounds__(256) void pe_fill_kernel(
    const float* __restrict__ q_b, const float* __restrict__ k_b,
    const float* __restrict__ v_b)
{
    int idx = blockIdx.x * 256 + threadIdx.x;
    if (idx < 256 * 128) {
        int r = idx >> 7, c = idx & 127;
        float v = pe_val(r, c);
        g_pe_imgK[idx] = v + k_b[c];
        g_pe_imgV[idx] = v + v_b[c];
    } else {
        int local = idx - 256 * 128;           // c * NTRI + n
        int c = local / NTRI, n = local - c * NTRI;
        g_pe_triT[local] = pe_val(n, c) + q_b[c];
    }
}

// ------------------- transposes: in_wT (Wk,Wv) + imgT ------------------------
__global__ __launch_bounds__(256) void transpose_all_kernel(
    const float* __restrict__ in_w, const float* __restrict__ img)
{
    __shared__ float s[32][33];
    int bid = blockIdx.x;
    int tid = threadIdx.x;
    int tx = tid & 31, ty = tid >> 5;
    if (bid < 32) {                      // Wk / Wv 128x128 transposes
        const float* src = in_w + (bid < 16 ? 128 * 128 : 256 * 128);
        float* dst = (bid < 16) ? g_WkT : g_WvT;
        int t = bid & 15;
        int r0 = (t >> 2) * 32, c0 = (t & 3) * 32;
#pragma unroll
        for (int i = 0; i < 4; i++)
            s[ty + i * 8][tx] = src[(r0 + ty + i * 8) * 128 + c0 + tx];
        __syncthreads();
#pragma unroll
        for (int i = 0; i < 4; i++)
            dst[(c0 + ty + i * 8) * 128 + r0 + tx] = s[tx][ty + i * 8];
    } else {                             // imgT: per (b,j) transpose 256x1280 -> 1280x256
        int t = bid - 32;                // 20 groups x 320 tiles
        int g = t / 320; t -= g * 320;
        int k0 = (t >> 3) * 32;          // 40 k-tiles
        int p0 = (t & 7) * 32;           // 8 p-tiles
        const float* src = img + (size_t)g * 257 * IMGC + IMGC;   // skip CLS
#pragma unroll
        for (int i = 0; i < 4; i++)
            s[ty + i * 8][tx] = src[(size_t)(p0 + ty + i * 8) * IMGC + k0 + tx];
        __syncthreads();
        float* dst = g_imgT + (size_t)g * IMGC * 256;
#pragma unroll
        for (int i = 0; i < 4; i++)
            dst[(size_t)(k0 + ty + i * 8) * 256 + p0 + tx] = s[tx][ty + i * 8];
    }
}

// ------------------- merged small precompute --------------------------------
// blocks [0,256): bKV row p ; [256,352): WcatT ; [352,384): WocT ; 384: boc
__global__ __launch_bounds__(256) void small_all_kernel(
    const float* __restrict__ in_w, const float* __restrict__ in_b,
    const float* __restrict__ q_w,
    const float* __restrict__ out_w, const float* __restrict__ out_b,
    const float* __restrict__ conv_w, const float* __restrict__ conv_b)
{
    const float* Wq = in_w;
    const float* Wk = in_w + 128 * 128;
    const float* Wv = in_w + 256 * 128;
    int bid = blockIdx.x, tid = threadIdx.x;
    if (bid < 256) {
        __shared__ float peK[128], peV[128];
        if (tid < 128) peK[tid] = g_pe_imgK[bid * 128 + tid];
        else           peV[tid - 128] = g_pe_imgV[bid * 128 + tid - 128];
        __syncthreads();
        float s;
        if (tid < 128) {
            s = in_b[128 + tid];
            const float* wr = Wk + tid * 128;
            for (int e = 0; e < 128; e++) s = fmaf(wr[e], peK[e], s);
        } else {
            int c = tid - 128;
            s = in_b[256 + c];
            const float* wr = Wv + c * 128;
            for (int e = 0; e < 128; e++) s = fmaf(wr[e], peV[e], s);
        }
        g_bKV[bid * 256 + tid] = s;
    } else if (bid < 352) {
        int idx = (bid - 256) * 256 + tid;   // 192*128, k*128+i
        int k = idx >> 7, i = idx & 127;
        float s;
        if (k < 64) {
            s = 0.f;
            for (int e = 0; e < 128; e++)
                s = fmaf(Wq[i * 128 + e], q_w[e * 64 + k], s);
        } else {
            s = Wq[i * 128 + (k - 64)];
        }
        g_WcatT[idx] = s;
    } else if (bid < 384) {
        int idx = (bid - 352) * 256 + tid;   // 128*64, c*64+oc
        int c = idx >> 6, oc = idx & 63;
        float s = 0.f;
        for (int d = 0; d < 128; d++)
            s = fmaf(conv_w[oc * 128 + d], out_w[d * 128 + c], s);
        g_WocT[idx] = s;
    } else if (tid < 64) {
        float s = conv_b[tid];
        for (int d = 0; d < 128; d++)
            s = fmaf(conv_w[tid * 128 + d], out_b[d], s);
        g_boc[tid] = s;
    }
}

// ------------------- FFMA2 SGEMM: K-major operands ---------------------------
struct GCfg {
    const float* A1; long long gdiv; long long gstride; int lda1;
    const float* A2; int lda2; long long mod2; int kSplit;
    const float* W; int ldw;
    const float* bias; const float* T; int t_mod; int ldt;
    float* C; int ldc; int K; int ny; int trans_rows;
};

__global__ __launch_bounds__(128, 4) void gemm_f2_kernel(GCfg c0, GCfg c1, int count0)
{
    const bool first = (blockIdx.x < (unsigned)count0);
    GCfg cfg = first ? c0 : c1;
    const int local = first ? blockIdx.x : blockIdx.x - count0;

    __shared__ __align__(16) float As[2][16][68];
    __shared__ __align__(16) float Ws[2][16][68];

    const int tid = threadIdx.x;
    const int tx = tid & 15, ty = tid >> 4;
    const int m0 = (local / cfg.ny) * 64;
    const int n0 = (local % cfg.ny) * 64;

    const int kr = tid >> 3;
    const int cq = (tid & 7) * 8;
    const long long cm = m0 + cq;
    const float* base1 = cfg.A1 + (cm / cfg.gdiv) * cfg.gstride + (cm % cfg.gdiv);
    const float* base2 = cfg.A2 ? (cfg.A2 + (cm % cfg.mod2)) : nullptr;
    const float* wbase = cfg.W + n0 + cq;
    const bool concat = (cfg.A2 != nullptr);

    unsigned long long acc[4][4];
#pragma unroll
    for (int i = 0; i < 4; i++)
#pragma unroll
        for (int j = 0; j < 4; j++) acc[i][j] = 0ULL;

    const int nk = cfg.K / 16;

    float4 a0, a1, w0, w1;
    {
        int kk = kr;
        const float* p = (concat && kk >= cfg.kSplit)
            ? base2 + (size_t)(kk - cfg.kSplit) * cfg.lda2
            : base1 + (size_t)kk * cfg.lda1;
        a0 = *(const float4*)p; a1 = *(const float4*)(p + 4);
        const float* q = wbase + (size_t)kk * cfg.ldw;
        w0 = *(const float4*)q; w1 = *(const float4*)(q + 4);
    }
    *(float4*)&As[0][kr][cq]     = a0;
    *(float4*)&As[0][kr][cq + 4] = a1;
    *(float4*)&Ws[0][kr][cq]     = w0;
    *(float4*)&Ws[0][kr][cq + 4] = w1;
    __syncthreads();

    for (int it = 0; it < nk; ++it) {
        const int cur = it & 1;
        const bool more = (it + 1 < nk);
        if (more) {
            int kk = (it + 1) * 16 + kr;
            const float* p = (concat && kk >= cfg.kSplit)
                ? base2 + (size_t)(kk - cfg.kSplit) * cfg.lda2
                : base1 + (size_t)kk * cfg.lda1;
            a0 = *(const float4*)p; a1 = *(const float4*)(p + 4);
            const float* q = wbase + (size_t)kk * cfg.ldw;
            w0 = *(const float4*)q; w1 = *(const float4*)(q + 4);
        }
#pragma unroll
        for (int k = 0; k < 16; ++k) {
            const float* arow = &As[cur][k][ty * 8];
            ulonglong2 p0 = *(const ulonglong2*)arow;
            ulonglong2 p1 = *(const ulonglong2*)(arow + 4);
            unsigned long long a2[4] = {p0.x, p0.y, p1.x, p1.y};
            float4 u = *(const float4*)&Ws[cur][k][tx * 4];
            unsigned long long w2[4] = {packdup(u.x), packdup(u.y),
                                        packdup(u.z), packdup(u.w)};
#pragma unroll
            for (int i = 0; i < 4; i++)
#pragma unroll
                for (int j = 0; j < 4; j++)
                    acc[i][j] = fma2(a2[i], w2[j], acc[i][j]);
        }
        if (more) {
            const int nxt = (it + 1) & 1;
            *(float4*)&As[nxt][kr][cq]     = a0;
            *(float4*)&As[nxt][kr][cq + 4] = a1;
            *(float4*)&Ws[nxt][kr][cq]     = w0;
            *(float4*)&Ws[nxt][kr][cq + 4] = w1;
        }
        __syncthreads();
    }

#pragma unroll
    for (int i = 0; i < 4; i++) {
        float clo[4], chi[4];
#pragma unroll
        for (int j = 0; j < 4; j++) unpack2(acc[i][j], clo[j], chi[j]);
#pragma unroll
        for (int h = 0; h < 2; h++) {
            const int m = m0 + ty * 8 + i * 2 + h;
            const int mt = cfg.T ? (m % cfg.t_mod) : 0;
            float4 v;
            float* vp = (float*)&v;
#pragma unroll
            for (int j = 0; j < 4; j++) {
                const int gn = n0 + tx * 4 + j;
                float x = h ? chi[j] : clo[j];
                if (cfg.bias) x += cfg.bias[gn];
                if (cfg.T)    x += cfg.T[(size_t)mt * cfg.ldt + gn];
                vp[j] = x;
            }
            *(float4*)(cfg.C + (size_t)m * cfg.ldc + n0 + tx * 4) = v;
        }
    }
}

// ------------------- dedicated final GEMM (K=128, N=64, transposed store) ----
__global__ __launch_bounds__(128, 5) void final_kernel(
    const float* __restrict__ oT, const float* __restrict__ WocT,
    const float* __restrict__ boc, float* __restrict__ out)
{
    __shared__ __align__(16) float SM[4 * 16 * 68];   // 17408B; Cs overlays
    float (*As)[16][68] = reinterpret_cast<float(*)[16][68]>(SM);
    float (*Ws)[16][68] = reinterpret_cast<float(*)[16][68]>(SM + 2 * 16 * 68);

    const int tid = threadIdx.x;
    const int tx = tid & 15, ty = tid >> 4;
    const int m0 = blockIdx.x * 64;

    const int kr = tid >> 3;
    const int cq = (tid & 7) * 8;
    const float* abase = oT + m0 + cq;          // + kk*NROWS
    const float* wbase = WocT + cq;             // + kk*64

    unsigned long long acc[4][4];
#pragma unroll
    for (int i = 0; i < 4; i++)
#pragma unroll
        for (int j = 0; j < 4; j++) acc[i][j] = 0ULL;

    float4 a0, a1, w0, w1;
    a0 = *(const float4*)(abase + (size_t)kr * NROWS);
    a1 = *(const float4*)(abase + (size_t)kr * NROWS + 4);
    w0 = *(const float4*)(wbase + (size_t)kr * 64);
    w1 = *(const float4*)(wbase + (size_t)kr * 64 + 4);
    *(float4*)&As[0][kr][cq]     = a0;
    *(float4*)&As[0][kr][cq + 4] = a1;
    *(float4*)&Ws[0][kr][cq]     = w0;
    *(float4*)&Ws[0][kr][cq + 4] = w1;
    __syncthreads();

    for (int it = 0; it < 8; ++it) {            // NOT unrolled: small I$ body
        const int cur = it & 1;
        if (it + 1 < 8) {
            int kk = (it + 1) * 16 + kr;
            a0 = *(const float4*)(abase + (size_t)kk * NROWS);
            a1 = *(const float4*)(abase + (size_t)kk * NROWS + 4);
            w0 = *(const float4*)(wbase + (size_t)kk * 64);
            w1 = *(const float4*)(wbase + (size_t)kk * 64 + 4);
        }
#pragma unroll
        for (int k = 0; k < 16; ++k) {
            const float* arow = &As[cur][k][ty * 8];
            ulonglong2 p0 = *(const ulonglong2*)arow;
            ulonglong2 p1 = *(const ulonglong2*)(arow + 4);
            unsigned long long a2[4] = {p0.x, p0.y, p1.x, p1.y};
            float4 u = *(const float4*)&Ws[cur][k][tx * 4];
            unsigned long long w2[4] = {packdup(u.x), packdup(u.y),
                                        packdup(u.z), packdup(u.w)};
#pragma unroll
            for (int i = 0; i < 4; i++)
#pragma unroll
                for (int j = 0; j < 4; j++)
                    acc[i][j] = fma2(a2[i], w2[j], acc[i][j]);
        }
        if (it + 1 < 8) {
            const int nxt = (it + 1) & 1;
            *(float4*)&As[nxt][kr][cq]     = a0;
            *(float4*)&As[nxt][kr][cq + 4] = a1;
            *(float4*)&Ws[nxt][kr][cq]     = w0;
            *(float4*)&Ws[nxt][kr][cq + 4] = w1;
        }
        __syncthreads();
    }

    // stage 64x64 tile in smem (overlaid), then coalesced transposed store
    float (*Cs)[65] = reinterpret_cast<float(*)[65]>(SM);
#pragma unroll
    for (int i = 0; i < 4; i++) {
        float clo[4], chi[4];
#pragma unroll
        for (int j = 0; j < 4; j++) unpack2(acc[i][j], clo[j], chi[j]);
#pragma unroll
        for (int j = 0; j < 4; j++) {
            const float bb = boc[tx * 4 + j];
            Cs[ty * 8 + i * 2 + 0][tx * 4 + j] = clo[j] + bb;
            Cs[ty * 8 + i * 2 + 1][tx * 4 + j] = chi[j] + bb;
        }
    }
    __syncthreads();
    const int oc = tid >> 1, half = tid & 1;
    const int bb = m0 / NTRI;
    const int nn0 = m0 - bb * NTRI;
    float* base = out + (size_t)(bb * 64 + oc) * NTRI + nn0 + half * 32;
#pragma unroll
    for (int s = 0; s < 8; s++) {
        float4 v;
        v.x = Cs[half * 32 + s * 4 + 0][oc];
        v.y = Cs[half * 32 + s * 4 + 1][oc];
        v.z = Cs[half * 32 + s * 4 + 2][oc];
        v.w = Cs[half * 32 + s * 4 + 3][oc];
        *(float4*)(base + s * 4) = v;
    }
}

// ------------------- fused sample + attention (writes oT) --------------------
__global__ __launch_bounds__(256) void fused_attn_kernel(const float* __restrict__ proj)
{
    __shared__ float Ps[NIM][12];
    __shared__ float o_s[8][132];
    const int b = blockIdx.y;
    if (threadIdx.x < NIM * 12) {
        int j = threadIdx.x / 12, e = threadIdx.x - j * 12;
        Ps[j][e] = proj[((size_t)(b * NIM + j) * 4 + (e >> 2)) * 4 + (e & 3)];
    }
    __syncthreads();

    const int lane = threadIdx.x & 31;
    const int wp = threadIdx.x >> 5;
    const int n = blockIdx.x * 8 + wp;

    const int plane = n >> 12;
    const int loc = n & 4095;
    const float colf = (float)(loc & 63);
    const float rowf = (float)(loc >> 6);
    float vx, vy, vz;
    if (plane == 0)      { vx = colf;  vy = 31.5f; vz = rowf; }
    else if (plane == 1) { vx = colf;  vy = rowf;  vz = 31.5f; }
    else                 { vx = 31.5f; vy = colf;  vz = rowf; }
    const float SC = (float)(2.0 * (1.0 + 0.1 + 1e-05));
    const float cx = (vx / 63.0f - 0.5f) * SC;
    const float cy = (vy / 63.0f - 0.5f) * SC;
    const float cz = (vz / 63.0f - 0.5f) * SC;

    const float4 q4 = *(const float4*)(g_qp + ((size_t)(b * NTRI + n)) * 128 + lane * 4);

    float4 vkeep[NIM];
    float score[NIM];

#pragma unroll
    for (int j = 0; j < NIM; ++j) {
        const float* P = Ps[j];
        float ci0 = cx * P[0] + cy * P[1] + cz * P[2]  + P[3];
        float ci1 = cx * P[4] + cy * P[5] + cz * P[6]  + P[7];
        float ci2 = cx * P[8] + cy * P[9] + cz * P[10] + P[11];
        float x = __fdividef(__fdividef(ci0, ci2), 223.0f);
        float y = __fdividef(__fdividef(ci1, ci2), 223.0f);
        float gx = fminf(fmaxf((x - 0.5f) * 2.0f, -1.0f), 1.0f);
        float gy = fminf(fmaxf((y - 0.5f) * 2.0f, -1.0f), 1.0f);
        float ix = (gx + 1.0f) * 7.5f;
        float iy = (gy + 1.0f) * 7.5f;
        float x0f = floorf(ix), y0f = floorf(iy);
        float wx = ix - x0f, wy = iy - y0f;
        int x0 = min(max((int)x0f, 0), 15);
        int x1 = min(x0 + 1, 15);
        int y0 = min(max((int)y0f, 0), 15);
        int y1 = min(y0 + 1, 15);
        float w00 = (1.f - wy) * (1.f - wx);
        float w01 = (1.f - wy) * wx;
        float w10 = wy * (1.f - wx);
        float w11 = wy * wx;

        const float* base = g_vol + (size_t)(b * NIM + j) * PTOK * 256;
        const int t00 = (y0 * 16 + x0) * 256, t01 = (y0 * 16 + x1) * 256;
        const int t10 = (y1 * 16 + x0) * 256, t11 = (y1 * 16 + x1) * 256;
        const int ck = lane * 4;

        float4 k00 = *(const float4*)(base + t00 + ck);
        float4 k01 = *(const float4*)(base + t01 + ck);
        float4 k10 = *(const float4*)(base + t10 + ck);
        float4 k11 = *(const float4*)(base + t11 + ck);

        float d00 = q4.x*k00.x; d00 = fmaf(q4.y,k00.y,d00); d00 = fmaf(q4.z,k00.z,d00); d00 = fmaf(q4.w,k00.w,d00);
        float d01 = q4.x*k01.x; d01 = fmaf(q4.y,k01.y,d01); d01 = fmaf(q4.z,k01.z,d01); d01 = fmaf(q4.w,k01.w,d01);
        float d10 = q4.x*k10.x; d10 = fmaf(q4.y,k10.y,d10); d10 = fmaf(q4.z,k10.z,d10); d10 = fmaf(q4.w,k10.w,d10);
        float d11 = q4.x*k11.x; d11 = fmaf(q4.y,k11.y,d11); d11 = fmaf(q4.z,k11.z,d11); d11 = fmaf(q4.w,k11.w,d11);
        float d = w00*d00; d = fmaf(w01,d01,d); d = fmaf(w10,d10,d); d = fmaf(w11,d11,d);
        d += __shfl_xor_sync(0xffffffffu, d, 1);
        d += __shfl_xor_sync(0xffffffffu, d, 2);
        score[j] = d * 0.25f;

        float4 v00 = *(const float4*)(base + t00 + 128 + ck);
        float4 v01 = *(const float4*)(base + t01 + 128 + ck);
        float4 v10 = *(const float4*)(base + t10 + 128 + ck);
        float4 v11 = *(const float4*)(base + t11 + 128 + ck);
        float4 vv;
        vv.x = w00*v00.x; vv.x = fmaf(w01,v01.x,vv.x); vv.x = fmaf(w10,v10.x,vv.x); vv.x = fmaf(w11,v11.x,vv.x);
        vv.y = w00*v00.y; vv.y = fmaf(w01,v01.y,vv.y); vv.y = fmaf(w10,v10.y,vv.y); vv.y = fmaf(w11,v11.y,vv.y);
        vv.z = w00*v00.z; vv.z = fmaf(w01,v01.z,vv.z); vv.z = fmaf(w10,v10.z,vv.z); vv.z = fmaf(w11,v11.z,vv.z);
        vv.w = w00*v00.w; vv.w = fmaf(w01,v01.w,vv.w); vv.w = fmaf(w10,v10.w,vv.w); vv.w = fmaf(w11,v11.w,vv.w);
        vkeep[j] = vv;
    }

    float mx = score[0];
#pragma unroll
    for (int j = 1; j < NIM; j++) mx = fmaxf(mx, score[j]);
    float sum = 0.f;
#pragma unroll
    for (int j = 0; j < NIM; j++) { score[j] = __expf(score[j] - mx); sum += score[j]; }
    const float inv = 1.f / sum;

    float4 o = make_float4(0.f, 0.f, 0.f, 0.f);
#pragma unroll
    for (int j = 0; j < NIM; j++) {
        float w = score[j] * inv;
        o.x = fmaf(w, vkeep[j].x, o.x);
        o.y = fmaf(w, vkeep[j].y, o.y);
        o.z = fmaf(w, vkeep[j].z, o.z);
        o.w = fmaf(w, vkeep[j].w, o.w);
    }
    o_s[wp][lane * 4 + 0] = o.x;
    o_s[wp][lane * 4 + 1] = o.y;
    o_s[wp][lane * 4 + 2] = o.z;
    o_s[wp][lane * 4 + 3] = o.w;
    __syncthreads();

    const int c = threadIdx.x >> 1, h = threadIdx.x & 1;
    float4 v;
    v.x = o_s[h * 4 + 0][c];
    v.y = o_s[h * 4 + 1][c];
    v.z = o_s[h * 4 + 2][c];
    v.w = o_s[h * 4 + 3][c];
    *(float4*)(g_oT + (size_t)c * NROWS + (size_t)b * NTRI + blockIdx.x * 8 + h * 4) = v;
}

// ------------------- launch -------------------------------------------------
extern "C" void kernel_launch(void* const* d_in, const int* in_sizes, int n_in,
                              void* d_out, int out_size)
{
    const float* tf     = (const float*)d_in[0];
    const float* img    = (const float*)d_in[1];
    const float* proj   = (const float*)d_in[2];
    const float* k_w    = (const float*)d_in[4];
    const float* k_b    = (const float*)d_in[5];
    const float* q_w    = (const float*)d_in[6];
    const float* q_b    = (const float*)d_in[7];
    const float* v_w    = (const float*)d_in[8];
    const float* v_b    = (const float*)d_in[9];
    const float* in_w   = (const float*)d_in[10];
    const float* in_b   = (const float*)d_in[11];
    const float* out_w  = (const float*)d_in[12];
    const float* out_b  = (const float*)d_in[13];
    const float* conv_w = (const float*)d_in[14];
    const float* conv_b = (const float*)d_in[15];
    float* out = (float*)d_out;

    float *p_WkT, *p_WvT, *p_WcT, *p_WcatT, *p_WocT, *p_bKV, *p_boc;
    float *p_pe_triT, *p_imgT, *p_vol, *p_qp, *p_oT;
    cudaGetSymbolAddress((void**)&p_WkT, g_WkT);
    cudaGetSymbolAddress((void**)&p_WvT, g_WvT);
    cudaGetSymbolAddress((void**)&p_WcT, g_WcT);
    cudaGetSymbolAddress((void**)&p_WcatT, g_WcatT);
    cudaGetSymbolAddress((void**)&p_WocT, g_WocT);
    cudaGetSymbolAddress((void**)&p_bKV, g_bKV);
    cudaGetSymbolAddress((void**)&p_boc, g_boc);
    cudaGetSymbolAddress((void**)&p_pe_triT, g_pe_triT);
    cudaGetSymbolAddress((void**)&p_imgT, g_imgT);
    cudaGetSymbolAddress((void**)&p_vol, g_vol);
    cudaGetSymbolAddress((void**)&p_qp,  g_qp);
    cudaGetSymbolAddress((void**)&p_oT,  g_oT);

    const long long BIG = 1LL << 60;

    // L1: PE tables (+folded biases)
    pe_fill_kernel<<<(256 * 128 + 128 * NTRI) / 256, 256>>>(q_b, k_b, v_b);
    // L2: transposes (WkT, WvT, imgT)
    transpose_all_kernel<<<32 + 20 * 320, 256>>>(in_w, img);
    // L3: small precomputes (bKV, WcatT, WocT, boc)
    small_all_kernel<<<385, 256>>>(in_w, in_b, q_w, out_w, out_b, conv_w, conv_b);

    // L4: WcT = [ (k_w^T Wk^T) | (v_w^T Wv^T) ]  -> [e][c], dual cfg 40+40 CTAs
    {
        GCfg ck = { k_w, BIG, 0, IMGC,  nullptr, 0, 1, 1 << 30,
                    p_WkT, 128, nullptr, nullptr, 1, 1,
                    p_WcT, 256, 128, 2, 0 };
        GCfg cv = { v_w, BIG, 0, IMGC,  nullptr, 0, 1, 1 << 30,
                    p_WvT, 128, nullptr, nullptr, 1, 1,
                    p_WcT + 128, 256, 128, 2, 0 };
        gemm_f2_kernel<<<80, 128>>>(ck, cv, 40);
    }

    // L5: mega GEMM: volKV (320 CTAs) + qp (1536 CTAs)
    {
        GCfg cvol = { p_imgT, 256, 1280LL * 256, 256,  nullptr, 0, 1, 1 << 30,
                      p_WcT, 256, nullptr, p_bKV, 256, 256,
                      p_vol, 256, IMGC, 4, 0 };
        GCfg cqp  = { tf, NTRI, 64LL * NTRI, NTRI,  p_pe_triT, NTRI, NTRI, 64,
                      p_WcatT, 128, in_b, nullptr, 1, 1,
                      p_qp, 128, 192, 2, 0 };
        gemm_f2_kernel<<<320 + 1536, 128>>>(cvol, cqp, 320);
    }

    // L6: fused sample + attention -> oT
    fused_attn_kernel<<<dim3(NTRI / 8, NB), 256>>>(proj);

    // L7: dedicated final GEMM (low-reg, overlaid smem, bounded I$ body)
    final_kernel<<<768, 128>>>(p_oT, p_WocT, p_boc, out);
}

// round 17
// speedup vs baseline: 1.1496x; 1.0108x over previous
#include <cuda_runtime.h>
#include <math.h>

#define NB    4
#define NIM   5
#define NTRI  12288
#define PTOK  256
#define IMGC  1280
#define EMB   128
#define NROWS (NB * NTRI)

// ------------------- scratch (device globals, no allocs) -------------------
__device__ float g_pe_imgK[256 * 128];             // pe_img + k_b
__device__ float g_pe_imgV[256 * 128];             // pe_img + v_b
__device__ float g_pe_triT[128 * NTRI];            // (pe_tri + q_b)^T  [c][n]
__device__ float g_WkT[128 * 128];                 // Wk^T
__device__ float g_WvT[128 * 128];                 // Wv^T
__device__ float g_WcT[IMGC * 256];                // [e][0:128]=Wk@k_w, [128:256]=Wv@v_w (K-major)
__device__ float g_WcatT[192 * 128];               // [k][i]: k<64 -> Wqc^T, else Wq^T
__device__ float g_WocT[128 * 64];                 // (conv_w@out_w)^T
__device__ float g_bKV[256 * 256];                 // [p][c] combined bias+pe for kv'
__device__ float g_boc[64];
__device__ float g_imgT[20LL * IMGC * 256];        // img tokens transposed  [g][k][p]  26MB
__device__ float g_vol[(size_t)NB * NIM * PTOK * 256];   // volKV' 5.2MB
__device__ float g_qp [(size_t)NROWS * EMB];       // 25MB
__device__ float g_oT [(size_t)EMB * NROWS];       // attention out, K-major  25MB

// ------------------- f32x2 helpers ------------------------------------------
__device__ __forceinline__ unsigned long long fma2(unsigned long long a,
                                                   unsigned long long b,
                                                   unsigned long long c) {
    unsigned long long d;
    asm("fma.rn.f32x2 %0, %1, %2, %3;" : "=l"(d) : "l"(a), "l"(b), "l"(c));
    return d;
}
__device__ __forceinline__ unsigned long long packdup(float x) {
    unsigned long long d;
    unsigned int u = __float_as_uint(x);
    asm("mov.b64 %0, {%1, %2};" : "=l"(d) : "r"(u), "r"(u));
    return d;
}
__device__ __forceinline__ void unpack2(unsigned long long v, float& lo, float& hi) {
    unsigned int a, b;
    asm("mov.b64 {%0, %1}, %2;" : "=r"(a), "=r"(b) : "l"(v));
    lo = __uint_as_float(a); hi = __uint_as_float(b);
}

// ------------------- fast fp32 positional encoding --------------------------
__device__ __forceinline__ float pe_val(int pos, int c) {
    int i = c >> 1;
    float divf = expf((float)(2 * i) * (-0.07195578415606394f));
    float a = (float)pos * divf;
    float kf = rintf(a * 0.6366197723675814f);
    float r = fmaf(-kf, 1.57079637050628662109375f, a);
    r = fmaf(-kf, -4.37113900018624283e-8f, r);
    float z = r * r;
    float p = fmaf(-1.9515295891e-4f, z, 8.3321608736e-3f);
    p = fmaf(p, z, -1.6666654611e-1f);
    float ps = fmaf(p * z, r, r);
    float q2 = fmaf(2.443315711809948e-5f, z, -1.388731625493765e-3f);
    q2 = fmaf(q2, z, 4.166664568298827e-2f);
    float pc = fmaf(q2, z * z, fmaf(-0.5f, z, 1.f));
    int qi = ((int)kf + (c & 1)) & 3;
    float res = (qi & 1) ? pc : ps;
    return (qi & 2) ? -res : res;
}

__global__ __launch_bounds__(256) void pe_fill_kernel(
    const float* __restrict__ q_b, const float* __restrict__ k_b,
    const float* __restrict__ v_b)
{
    int idx = blockIdx.x * 256 + threadIdx.x;
    if (idx < 256 * 128) {
        int r = idx >> 7, c = idx & 127;
        float v = pe_val(r, c);
        g_pe_imgK[idx] = v + k_b[c];
        g_pe_imgV[idx] = v + v_b[c];
    } else {
        int local = idx - 256 * 128;           // c * NTRI + n
        int c = local / NTRI, n = local - c * NTRI;
        g_pe_triT[local] = pe_val(n, c) + q_b[c];
    }
}

// ------------------- transposes: in_wT (Wk,Wv) + imgT ------------------------
__global__ __launch_bounds__(256) void transpose_all_kernel(
    const float* __restrict__ in_w, const float* __restrict__ img)
{
    __shared__ float s[32][33];
    int bid = blockIdx.x;
    int tid = threadIdx.x;
    int tx = tid & 31, ty = tid >> 5;
    if (bid < 32) {                      // Wk / Wv 128x128 transposes
        const float* src = in_w + (bid < 16 ? 128 * 128 : 256 * 128);
        float* dst = (bid < 16) ? g_WkT : g_WvT;
        int t = bid & 15;
        int r0 = (t >> 2) * 32, c0 = (t & 3) * 32;
#pragma unroll
        for (int i = 0; i < 4; i++)
            s[ty + i * 8][tx] = src[(r0 + ty + i * 8) * 128 + c0 + tx];
        __syncthreads();
#pragma unroll
        for (int i = 0; i < 4; i++)
            dst[(c0 + ty + i * 8) * 128 + r0 + tx] = s[tx][ty + i * 8];
    } else {                             // imgT: per (b,j) transpose 256x1280 -> 1280x256
        int t = bid - 32;                // 20 groups x 320 tiles
        int g = t / 320; t -= g * 320;
        int k0 = (t >> 3) * 32;          // 40 k-tiles
        int p0 = (t & 7) * 32;           // 8 p-tiles
        const float* src = img + (size_t)g * 257 * IMGC + IMGC;   // skip CLS
#pragma unroll
        for (int i = 0; i < 4; i++)
            s[ty + i * 8][tx] = src[(size_t)(p0 + ty + i * 8) * IMGC + k0 + tx];
        __syncthreads();
        float* dst = g_imgT + (size_t)g * IMGC * 256;
#pragma unroll
        for (int i = 0; i < 4; i++)
            dst[(size_t)(k0 + ty + i * 8) * 256 + p0 + tx] = s[tx][ty + i * 8];
    }
}

// ------------------- merged small precompute --------------------------------
// blocks [0,256): bKV row p ; [256,352): WcatT ; [352,384): WocT ; 384: boc
__global__ __launch_bounds__(256) void small_all_kernel(
    const float* __restrict__ in_w, const float* __restrict__ in_b,
    const float* __restrict__ q_w,
    const float* __restrict__ out_w, const float* __restrict__ out_b,
    const float* __restrict__ conv_w, const float* __restrict__ conv_b)
{
    const float* Wq = in_w;
    const float* Wk = in_w + 128 * 128;
    const float* Wv = in_w + 256 * 128;
    int bid = blockIdx.x, tid = threadIdx.x;
    if (bid < 256) {
        __shared__ float peK[128], peV[128];
        if (tid < 128) peK[tid] = g_pe_imgK[bid * 128 + tid];
        else           peV[tid - 128] = g_pe_imgV[bid * 128 + tid - 128];
        __syncthreads();
        float s;
        if (tid < 128) {
            s = in_b[128 + tid];
            const float* wr = Wk + tid * 128;
            for (int e = 0; e < 128; e++) s = fmaf(wr[e], peK[e], s);
        } else {
            int c = tid - 128;
            s = in_b[256 + c];
            const float* wr = Wv + c * 128;
            for (int e = 0; e < 128; e++) s = fmaf(wr[e], peV[e], s);
        }
        g_bKV[bid * 256 + tid] = s;
    } else if (bid < 352) {
        int idx = (bid - 256) * 256 + tid;   // 192*128, k*128+i
        int k = idx >> 7, i = idx & 127;
        float s;
        if (k < 64) {
            s = 0.f;
            for (int e = 0; e < 128; e++)
                s = fmaf(Wq[i * 128 + e], q_w[e * 64 + k], s);
        } else {
            s = Wq[i * 128 + (k - 64)];
        }
        g_WcatT[idx] = s;
    } else if (bid < 384) {
        int idx = (bid - 352) * 256 + tid;   // 128*64, c*64+oc
        int c = idx >> 6, oc = idx & 63;
        float s = 0.f;
        for (int d = 0; d < 128; d++)
            s = fmaf(conv_w[oc * 128 + d], out_w[d * 128 + c], s);
        g_WocT[idx] = s;
    } else if (tid < 64) {
        float s = conv_b[tid];
        for (int d = 0; d < 128; d++)
            s = fmaf(conv_w[tid * 128 + d], out_b[d], s);
        g_boc[tid] = s;
    }
}

// ------------------- FFMA2 SGEMM: K-major operands ---------------------------
struct GCfg {
    const float* A1; long long gdiv; long long gstride; int lda1;
    const float* A2; int lda2; long long mod2; int kSplit;
    const float* W; int ldw;
    const float* bias; const float* T; int t_mod; int ldt;
    float* C; int ldc; int K; int ny; int trans_rows;
};

__global__ __launch_bounds__(128, 4) void gemm_f2_kernel(GCfg c0, GCfg c1, int count0)
{
    const bool first = (blockIdx.x < (unsigned)count0);
    GCfg cfg = first ? c0 : c1;
    const int local = first ? blockIdx.x : blockIdx.x - count0;

    __shared__ __align__(16) float As[2][16][68];
    __shared__ __align__(16) float Ws[2][16][68];

    const int tid = threadIdx.x;
    const int tx = tid & 15, ty = tid >> 4;
    const int m0 = (local / cfg.ny) * 64;
    const int n0 = (local % cfg.ny) * 64;

    const int kr = tid >> 3;
    const int cq = (tid & 7) * 8;
    const long long cm = m0 + cq;
    const float* base1 = cfg.A1 + (cm / cfg.gdiv) * cfg.gstride + (cm % cfg.gdiv);
    const float* base2 = cfg.A2 ? (cfg.A2 + (cm % cfg.mod2)) : nullptr;
    const float* wbase = cfg.W + n0 + cq;
    const bool concat = (cfg.A2 != nullptr);

    unsigned long long acc[4][4];
#pragma unroll
    for (int i = 0; i < 4; i++)
#pragma unroll
        for (int j = 0; j < 4; j++) acc[i][j] = 0ULL;

    const int nk = cfg.K / 16;

    float4 a0, a1, w0, w1;
    {
        int kk = kr;
        const float* p = (concat && kk >= cfg.kSplit)
            ? base2 + (size_t)(kk - cfg.kSplit) * cfg.lda2
            : base1 + (size_t)kk * cfg.lda1;
        a0 = *(const float4*)p; a1 = *(const float4*)(p + 4);
        const float* q = wbase + (size_t)kk * cfg.ldw;
        w0 = *(const float4*)q; w1 = *(const float4*)(q + 4);
    }
    *(float4*)&As[0][kr][cq]     = a0;
    *(float4*)&As[0][kr][cq + 4] = a1;
    *(float4*)&Ws[0][kr][cq]     = w0;
    *(float4*)&Ws[0][kr][cq + 4] = w1;
    __syncthreads();

    for (int it = 0; it < nk; ++it) {
        const int cur = it & 1;
        const bool more = (it + 1 < nk);
        if (more) {
            int kk = (it + 1) * 16 + kr;
            const float* p = (concat && kk >= cfg.kSplit)
                ? base2 + (size_t)(kk - cfg.kSplit) * cfg.lda2
                : base1 + (size_t)kk * cfg.lda1;
            a0 = *(const float4*)p; a1 = *(const float4*)(p + 4);
            const float* q = wbase + (size_t)kk * cfg.ldw;
            w0 = *(const float4*)q; w1 = *(const float4*)(q + 4);
        }
#pragma unroll
        for (int k = 0; k < 16; ++k) {
            const float* arow = &As[cur][k][ty * 8];
            ulonglong2 p0 = *(const ulonglong2*)arow;
            ulonglong2 p1 = *(const ulonglong2*)(arow + 4);
            unsigned long long a2[4] = {p0.x, p0.y, p1.x, p1.y};
            float4 u = *(const float4*)&Ws[cur][k][tx * 4];
            unsigned long long w2[4] = {packdup(u.x), packdup(u.y),
                                        packdup(u.z), packdup(u.w)};
#pragma unroll
            for (int i = 0; i < 4; i++)
#pragma unroll
                for (int j = 0; j < 4; j++)
                    acc[i][j] = fma2(a2[i], w2[j], acc[i][j]);
        }
        if (more) {
            const int nxt = (it + 1) & 1;
            *(float4*)&As[nxt][kr][cq]     = a0;
            *(float4*)&As[nxt][kr][cq + 4] = a1;
            *(float4*)&Ws[nxt][kr][cq]     = w0;
            *(float4*)&Ws[nxt][kr][cq + 4] = w1;
        }
        __syncthreads();
    }

#pragma unroll
    for (int i = 0; i < 4; i++) {
        float clo[4], chi[4];
#pragma unroll
        for (int j = 0; j < 4; j++) unpack2(acc[i][j], clo[j], chi[j]);
#pragma unroll
        for (int h = 0; h < 2; h++) {
            const int m = m0 + ty * 8 + i * 2 + h;
            const int mt = cfg.T ? (m % cfg.t_mod) : 0;
            float4 v;
            float* vp = (float*)&v;
#pragma unroll
            for (int j = 0; j < 4; j++) {
                const int gn = n0 + tx * 4 + j;
                float x = h ? chi[j] : clo[j];
                if (cfg.bias) x += cfg.bias[gn];
                if (cfg.T)    x += cfg.T[(size_t)mt * cfg.ldt + gn];
                vp[j] = x;
            }
            *(float4*)(cfg.C + (size_t)m * cfg.ldc + n0 + tx * 4) = v;
        }
    }
}

// ------------------- dedicated final GEMM (K=128, N=64, transposed store) ----
__global__ __launch_bounds__(128, 5) void final_kernel(
    const float* __restrict__ oT, const float* __restrict__ WocT,
    const float* __restrict__ boc, float* __restrict__ out)
{
    __shared__ __align__(16) float SM[4 * 16 * 68];   // 17408B; Cs overlays
    float (*As)[16][68] = reinterpret_cast<float(*)[16][68]>(SM);
    float (*Ws)[16][68] = reinterpret_cast<float(*)[16][68]>(SM + 2 * 16 * 68);

    const int tid = threadIdx.x;
    const int tx = tid & 15, ty = tid >> 4;
    const int m0 = blockIdx.x * 64;

    const int kr = tid >> 3;
    const int cq = (tid & 7) * 8;
    const float* abase = oT + m0 + cq;          // + kk*NROWS
    const float* wbase = WocT + cq;             // + kk*64

    unsigned long long acc[4][4];
#pragma unroll
    for (int i = 0; i < 4; i++)
#pragma unroll
        for (int j = 0; j < 4; j++) acc[i][j] = 0ULL;

    float4 a0, a1, w0, w1;
    a0 = *(const float4*)(abase + (size_t)kr * NROWS);
    a1 = *(const float4*)(abase + (size_t)kr * NROWS + 4);
    w0 = *(const float4*)(wbase + (size_t)kr * 64);
    w1 = *(const float4*)(wbase + (size_t)kr * 64 + 4);
    *(float4*)&As[0][kr][cq]     = a0;
    *(float4*)&As[0][kr][cq + 4] = a1;
    *(float4*)&Ws[0][kr][cq]     = w0;
    *(float4*)&Ws[0][kr][cq + 4] = w1;
    __syncthreads();

    for (int it = 0; it < 8; ++it) {            // NOT unrolled: small I$ body
        const int cur = it & 1;
        if (it + 1 < 8) {
            int kk = (it + 1) * 16 + kr;
            a0 = *(const float4*)(abase + (size_t)kk * NROWS);
            a1 = *(const float4*)(abase + (size_t)kk * NROWS + 4);
            w0 = *(const float4*)(wbase + (size_t)kk * 64);
            w1 = *(const float4*)(wbase + (size_t)kk * 64 + 4);
        }
#pragma unroll
        for (int k = 0; k < 16; ++k) {
            const float* arow = &As[cur][k][ty * 8];
            ulonglong2 p0 = *(const ulonglong2*)arow;
            ulonglong2 p1 = *(const ulonglong2*)(arow + 4);
            unsigned long long a2[4] = {p0.x, p0.y, p1.x, p1.y};
            float4 u = *(const float4*)&Ws[cur][k][tx * 4];
            unsigned long long w2[4] = {packdup(u.x), packdup(u.y),
                                        packdup(u.z), packdup(u.w)};
#pragma unroll
            for (int i = 0; i < 4; i++)
#pragma unroll
                for (int j = 0; j < 4; j++)
                    acc[i][j] = fma2(a2[i], w2[j], acc[i][j]);
        }
        if (it + 1 < 8) {
            const int nxt = (it + 1) & 1;
            *(float4*)&As[nxt][kr][cq]     = a0;
            *(float4*)&As[nxt][kr][cq + 4] = a1;
            *(float4*)&Ws[nxt][kr][cq]     = w0;
            *(float4*)&Ws[nxt][kr][cq + 4] = w1;
        }
        __syncthreads();
    }

    // stage 64x64 tile in smem (overlaid), then coalesced transposed store
    float (*Cs)[65] = reinterpret_cast<float(*)[65]>(SM);
#pragma unroll
    for (int i = 0; i < 4; i++) {
        float clo[4], chi[4];
#pragma unroll
        for (int j = 0; j < 4; j++) unpack2(acc[i][j], clo[j], chi[j]);
#pragma unroll
        for (int j = 0; j < 4; j++) {
            const float bb = boc[tx * 4 + j];
            Cs[ty * 8 + i * 2 + 0][tx * 4 + j] = clo[j] + bb;
            Cs[ty * 8 + i * 2 + 1][tx * 4 + j] = chi[j] + bb;
        }
    }
    __syncthreads();
    const int oc = tid >> 1, half = tid & 1;
    const int bb = m0 / NTRI;
    const int nn0 = m0 - bb * NTRI;
    float* base = out + (size_t)(bb * 64 + oc) * NTRI + nn0 + half * 32;
#pragma unroll
    for (int s = 0; s < 8; s++) {
        float4 v;
        v.x = Cs[half * 32 + s * 4 + 0][oc];
        v.y = Cs[half * 32 + s * 4 + 1][oc];
        v.z = Cs[half * 32 + s * 4 + 2][oc];
        v.w = Cs[half * 32 + s * 4 + 3][oc];
        *(float4*)(base + s * 4) = v;
    }
}

// ------------------- fused sample + attention (writes oT) --------------------
__global__ __launch_bounds__(256) void fused_attn_kernel(const float* __restrict__ proj)
{
    __shared__ float Ps[NIM][12];
    __shared__ float o_s[8][132];
    const int b = blockIdx.y;
    if (threadIdx.x < NIM * 12) {
        int j = threadIdx.x / 12, e = threadIdx.x - j * 12;
        Ps[j][e] = proj[((size_t)(b * NIM + j) * 4 + (e >> 2)) * 4 + (e & 3)];
    }
    __syncthreads();

    const int lane = threadIdx.x & 31;
    const int wp = threadIdx.x >> 5;
    const int n = blockIdx.x * 8 + wp;

    const int plane = n >> 12;
    const int loc = n & 4095;
    const float colf = (float)(loc & 63);
    const float rowf = (float)(loc >> 6);
    float vx, vy, vz;
    if (plane == 0)      { vx = colf;  vy = 31.5f; vz = rowf; }
    else if (plane == 1) { vx = colf;  vy = rowf;  vz = 31.5f; }
    else                 { vx = 31.5f; vy = colf;  vz = rowf; }
    const float SC = (float)(2.0 * (1.0 + 0.1 + 1e-05));
    const float cx = (vx / 63.0f - 0.5f) * SC;
    const float cy = (vy / 63.0f - 0.5f) * SC;
    const float cz = (vz / 63.0f - 0.5f) * SC;

    const float4 q4 = *(const float4*)(g_qp + ((size_t)(b * NTRI + n)) * 128 + lane * 4);

    float4 vkeep[NIM];
    float score[NIM];

#pragma unroll
    for (int j = 0; j < NIM; ++j) {
        const float* P = Ps[j];
        float ci0 = cx * P[0] + cy * P[1] + cz * P[2]  + P[3];
        float ci1 = cx * P[4] + cy * P[5] + cz * P[6]  + P[7];
        float ci2 = cx * P[8] + cy * P[9] + cz * P[10] + P[11];
        float x = __fdividef(__fdividef(ci0, ci2), 223.0f);
        float y = __fdividef(__fdividef(ci1, ci2), 223.0f);
        float gx = fminf(fmaxf((x - 0.5f) * 2.0f, -1.0f), 1.0f);
        float gy = fminf(fmaxf((y - 0.5f) * 2.0f, -1.0f), 1.0f);
        float ix = (gx + 1.0f) * 7.5f;       // in [0, 15]
        float iy = (gy + 1.0f) * 7.5f;
        int x0 = __float2int_rd(ix);         // 0..15, clamps provably dead
        int y0 = __float2int_rd(iy);
        float wx = ix - (float)x0;
        float wy = iy - (float)y0;
        int x1 = min(x0 + 1, 15);
        int y1 = min(y0 + 1, 15);
        float w00 = (1.f - wy) * (1.f - wx);
        float w01 = (1.f - wy) * wx;
        float w10 = wy * (1.f - wx);
        float w11 = wy * wx;

        const float* base = g_vol + (size_t)(b * NIM + j) * PTOK * 256;
        const int t00 = (y0 * 16 + x0) * 256, t01 = (y0 * 16 + x1) * 256;
        const int t10 = (y1 * 16 + x0) * 256, t11 = (y1 * 16 + x1) * 256;
        const int ck = lane * 4;

        float4 k00 = *(const float4*)(base + t00 + ck);
        float4 k01 = *(const float4*)(base + t01 + ck);
        float4 k10 = *(const float4*)(base + t10 + ck);
        float4 k11 = *(const float4*)(base + t11 + ck);

        float d00 = q4.x*k00.x; d00 = fmaf(q4.y,k00.y,d00); d00 = fmaf(q4.z,k00.z,d00); d00 = fmaf(q4.w,k00.w,d00);
        float d01 = q4.x*k01.x; d01 = fmaf(q4.y,k01.y,d01); d01 = fmaf(q4.z,k01.z,d01); d01 = fmaf(q4.w,k01.w,d01);
        float d10 = q4.x*k10.x; d10 = fmaf(q4.y,k10.y,d10); d10 = fmaf(q4.z,k10.z,d10); d10 = fmaf(q4.w,k10.w,d10);
        float d11 = q4.x*k11.x; d11 = fmaf(q4.y,k11.y,d11); d11 = fmaf(q4.z,k11.z,d11); d11 = fmaf(q4.w,k11.w,d11);
        float d = w00*d00; d = fmaf(w01,d01,d); d = fmaf(w10,d10,d); d = fmaf(w11,d11,d);
        d += __shfl_xor_sync(0xffffffffu, d, 1);
        d += __shfl_xor_sync(0xffffffffu, d, 2);
        score[j] = d * 0.25f;

        float4 v00 = *(const float4*)(base + t00 + 128 + ck);
        float4 v01 = *(const float4*)(base + t01 + 128 + ck);
        float4 v10 = *(const float4*)(base + t10 + 128 + ck);
        float4 v11 = *(const float4*)(base + t11 + 128 + ck);
        float4 vv;
        vv.x = w00*v00.x; vv.x = fmaf(w01,v01.x,vv.x); vv.x = fmaf(w10,v10.x,vv.x); vv.x = fmaf(w11,v11.x,vv.x);
        vv.y = w00*v00.y; vv.y = fmaf(w01,v01.y,vv.y); vv.y = fmaf(w10,v10.y,vv.y); vv.y = fmaf(w11,v11.y,vv.y);
        vv.z = w00*v00.z; vv.z = fmaf(w01,v01.z,vv.z); vv.z = fmaf(w10,v10.z,vv.z); vv.z = fmaf(w11,v11.z,vv.z);
        vv.w = w00*v00.w; vv.w = fmaf(w01,v01.w,vv.w); vv.w = fmaf(w10,v10.w,vv.w); vv.w = fmaf(w11,v11.w,vv.w);
        vkeep[j] = vv;
    }

    // softmax without max-subtraction (scores are O(1); no overflow risk)
    float sum = 0.f;
#pragma unroll
    for (int j = 0; j < NIM; j++) { score[j] = __expf(score[j]); sum += score[j]; }
    const float inv = 1.f / sum;

    float4 o = make_float4(0.f, 0.f, 0.f, 0.f);
#pragma unroll
    for (int j = 0; j < NIM; j++) {
        float w = score[j] * inv;
        o.x = fmaf(w, vkeep[j].x, o.x);
        o.y = fmaf(w, vkeep[j].y, o.y);
        o.z = fmaf(w, vkeep[j].z, o.z);
        o.w = fmaf(w, vkeep[j].w, o.w);
    }
    o_s[wp][lane * 4 + 0] = o.x;
    o_s[wp][lane * 4 + 1] = o.y;
    o_s[wp][lane * 4 + 2] = o.z;
    o_s[wp][lane * 4 + 3] = o.w;
    __syncthreads();

    const int c = threadIdx.x >> 1, h = threadIdx.x & 1;
    float4 v;
    v.x = o_s[h * 4 + 0][c];
    v.y = o_s[h * 4 + 1][c];
    v.z = o_s[h * 4 + 2][c];
    v.w = o_s[h * 4 + 3][c];
    *(float4*)(g_oT + (size_t)c * NROWS + (size_t)b * NTRI + blockIdx.x * 8 + h * 4) = v;
}

// ------------------- launch -------------------------------------------------
extern "C" void kernel_launch(void* const* d_in, const int* in_sizes, int n_in,
                              void* d_out, int out_size)
{
    const float* tf     = (const float*)d_in[0];
    const float* img    = (const float*)d_in[1];
    const float* proj   = (const float*)d_in[2];
    const float* k_w    = (const float*)d_in[4];
    const float* k_b    = (const float*)d_in[5];
    const float* q_w    = (const float*)d_in[6];
    const float* q_b    = (const float*)d_in[7];
    const float* v_w    = (const float*)d_in[8];
    const float* v_b    = (const float*)d_in[9];
    const float* in_w   = (const float*)d_in[10];
    const float* in_b   = (const float*)d_in[11];
    const float* out_w  = (const float*)d_in[12];
    const float* out_b  = (const float*)d_in[13];
    const float* conv_w = (const float*)d_in[14];
    const float* conv_b = (const float*)d_in[15];
    float* out = (float*)d_out;

    float *p_WkT, *p_WvT, *p_WcT, *p_WcatT, *p_WocT, *p_bKV, *p_boc;
    float *p_pe_triT, *p_imgT, *p_vol, *p_qp, *p_oT;
    cudaGetSymbolAddress((void**)&p_WkT, g_WkT);
    cudaGetSymbolAddress((void**)&p_WvT, g_WvT);
    cudaGetSymbolAddress((void**)&p_WcT, g_WcT);
    cudaGetSymbolAddress((void**)&p_WcatT, g_WcatT);
    cudaGetSymbolAddress((void**)&p_WocT, g_WocT);
    cudaGetSymbolAddress((void**)&p_bKV, g_bKV);
    cudaGetSymbolAddress((void**)&p_boc, g_boc);
    cudaGetSymbolAddress((void**)&p_pe_triT, g_pe_triT);
    cudaGetSymbolAddress((void**)&p_imgT, g_imgT);
    cudaGetSymbolAddress((void**)&p_vol, g_vol);
    cudaGetSymbolAddress((void**)&p_qp,  g_qp);
    cudaGetSymbolAddress((void**)&p_oT,  g_oT);

    const long long BIG = 1LL << 60;

    // L1: PE tables (+folded biases)
    pe_fill_kernel<<<(256 * 128 + 128 * NTRI) / 256, 256>>>(q_b, k_b, v_b);
    // L2: transposes (WkT, WvT, imgT)
    transpose_all_kernel<<<32 + 20 * 320, 256>>>(in_w, img);
    // L3: small precomputes (bKV, WcatT, WocT, boc)
    small_all_kernel<<<385, 256>>>(in_w, in_b, q_w, out_w, out_b, conv_w, conv_b);

    // L4: WcT = [ (k_w^T Wk^T) | (v_w^T Wv^T) ]  -> [e][c], dual cfg 40+40 CTAs
    {
        GCfg ck = { k_w, BIG, 0, IMGC,  nullptr, 0, 1, 1 << 30,
                    p_WkT, 128, nullptr, nullptr, 1, 1,
                    p_WcT, 256, 128, 2, 0 };
        GCfg cv = { v_w, BIG, 0, IMGC,  nullptr, 0, 1, 1 << 30,
                    p_WvT, 128, nullptr, nullptr, 1, 1,
                    p_WcT + 128, 256, 128, 2, 0 };
        gemm_f2_kernel<<<80, 128>>>(ck, cv, 40);
    }

    // L5: mega GEMM: volKV (320 CTAs) + qp (1536 CTAs)
    {
        GCfg cvol = { p_imgT, 256, 1280LL * 256, 256,  nullptr, 0, 1, 1 << 30,
                      p_WcT, 256, nullptr, p_bKV, 256, 256,
                      p_vol, 256, IMGC, 4, 0 };
        GCfg cqp  = { tf, NTRI, 64LL * NTRI, NTRI,  p_pe_triT, NTRI, NTRI, 64,
                      p_WcatT, 128, in_b, nullptr, 1, 1,
                      p_qp, 128, 192, 2, 0 };
        gemm_f2_kernel<<<320 + 1536, 128>>>(cvol, cqp, 320);
    }

    // L6: fused sample + attention -> oT
    fused_attn_kernel<<<dim3(NTRI / 8, NB), 256>>>(proj);

    // L7: dedicated final GEMM (low-reg, overlaid smem, bounded I$ body)
    final_kernel<<<768, 128>>>(p_oT, p_WocT, p_boc, out);
}